// round 10
// baseline (speedup 1.0000x reference)
#include <cuda_runtime.h>
#include <cuda_fp16.h>
#include <cuda_bf16.h>
#include <cstdint>

// Shapes (fixed by the problem)
#define B_   4
#define L_   4096
#define E_   1024
#define HID_ 4096
#define ROWS (B_ * L_)        // 16384
#define DH   64               // head dim
#define HEADS_ 16

// ---------------------------------------------------------------------------
// PTX helpers (sm_103-safe: no tcgen05)
// ---------------------------------------------------------------------------
__device__ __forceinline__ uint32_t smem_to_u32(const void* p) {
    uint32_t a;
    asm("{ .reg .u64 t; cvta.to.shared.u64 t, %1; cvt.u32.u64 %0, t; }" : "=r"(a) : "l"(p));
    return a;
}
#define CP_ASYNC16(dst, src) asm volatile("cp.async.cg.shared.global [%0], [%1], 16;" :: "r"((uint32_t)(dst)), "l"(src) : "memory")
#define CP_COMMIT()          asm volatile("cp.async.commit_group;" ::: "memory")
#define CP_WAIT(N)           asm volatile("cp.async.wait_group %0;" :: "n"(N) : "memory")

#define LDM_X4(r0, r1, r2, r3, addr) \
    asm volatile("ldmatrix.sync.aligned.m8n8.x4.shared.b16 {%0,%1,%2,%3}, [%4];" \
        : "=r"(r0), "=r"(r1), "=r"(r2), "=r"(r3) : "r"(addr))

__device__ __forceinline__ void mma_fp16(float* c, const uint32_t* a, const uint32_t* b) {
    asm volatile("mma.sync.aligned.m16n8k16.row.col.f32.f16.f16.f32 "
        "{%0,%1,%2,%3}, {%4,%5,%6,%7}, {%8,%9}, {%0,%1,%2,%3};"
        : "+f"(c[0]), "+f"(c[1]), "+f"(c[2]), "+f"(c[3])
        : "r"(a[0]), "r"(a[1]), "r"(a[2]), "r"(a[3]), "r"(b[0]), "r"(b[1]));
}

// Rows are 128B wide; XOR 16B columns with (row & 7) -> conflict-free ldmatrix
#define SWZOFF(row, col16) (((uint32_t)(row) * 128u) + ((((uint32_t)(col16)) ^ ((uint32_t)(row) & 7u)) << 4))

// ---------------------------------------------------------------------------
// Scratch (device globals)
// ---------------------------------------------------------------------------
__device__ float g_wvred[E_ * DH];
__device__ __half g_Sh[E_ * E_];
__device__ __half g_Sl[E_ * E_];
__device__ float g_AOproj[B_ * 256 * E_];
__device__ __half g_h1h[(size_t)ROWS * E_];
__device__ __half g_h1l[(size_t)ROWS * E_];
__device__ __half g_t[(size_t)ROWS * HID_];
__device__ __half g_wtoh[(size_t)E_ * E_];
__device__ __half g_wtol[(size_t)E_ * E_];
__device__ __half g_wt1[(size_t)HID_ * E_];
__device__ __half g_wt2[(size_t)HID_ * E_];
__device__ int g_cnt[ROWS / 128];            // per-t-row-block completion counters

// ---------------------------------------------------------------------------
// zero the producer counters (run each call: deterministic)
// ---------------------------------------------------------------------------
__global__ void zero_cnt_kernel() { g_cnt[threadIdx.x] = 0; }

// ---------------------------------------------------------------------------
// wv_red[e,d] = sum_h w_v[e, h*64+d]
// ---------------------------------------------------------------------------
__global__ void reduce_wv_kernel(const float* __restrict__ w_v) {
    int e = blockIdx.x, d = threadIdx.x;
    const float* row = w_v + (size_t)e * E_;
    float s = 0.f;
#pragma unroll
    for (int h = 0; h < HEADS_; h++) s += row[h * DH + d];
    g_wvred[e * DH + d] = s;
}

// ---------------------------------------------------------------------------
// S = x @ wv_red  (16384 x 64, K=1024) -> fp16 hi/lo split; 16 rows/block
// ---------------------------------------------------------------------------
__global__ __launch_bounds__(256) void gemm_S_kernel(const float* __restrict__ x) {
    int d = threadIdx.x;
    int mi = threadIdx.y;
    size_t m0 = (size_t)blockIdx.x * 16 + mi * 4;
    const float* xr0 = x + m0 * E_;
    const float* xr1 = xr0 + E_;
    const float* xr2 = xr1 + E_;
    const float* xr3 = xr2 + E_;
    float a0 = 0.f, a1 = 0.f, a2 = 0.f, a3 = 0.f;
#pragma unroll 4
    for (int k = 0; k < E_; k++) {
        float w = g_wvred[k * DH + d];
        a0 = fmaf(xr0[k], w, a0);
        a1 = fmaf(xr1[k], w, a1);
        a2 = fmaf(xr2[k], w, a2);
        a3 = fmaf(xr3[k], w, a3);
    }
    float av[4] = {a0, a1, a2, a3};
#pragma unroll
    for (int j = 0; j < 4; j++) {
        __half hi = __float2half_rn(av[j]);
        g_Sh[(m0 + j) * DH + d] = hi;
        g_Sl[(m0 + j) * DH + d] = __float2half_rn(av[j] - __half2float(hi));
    }
}

// ---------------------------------------------------------------------------
// Transpose fp32 -> fp16 (single). T[c, r] = half(W[r, c])
// ---------------------------------------------------------------------------
__global__ __launch_bounds__(256) void transpose_half_kernel(
    const float* __restrict__ W, int R, int C, __half* __restrict__ T) {
    __shared__ float tile[32][33];
    int r0 = blockIdx.y * 32, c0 = blockIdx.x * 32;
    int tx = threadIdx.x, ty = threadIdx.y;
#pragma unroll
    for (int j = 0; j < 4; j++)
        tile[ty + 8 * j][tx] = W[(size_t)(r0 + ty + 8 * j) * C + c0 + tx];
    __syncthreads();
#pragma unroll
    for (int j = 0; j < 4; j++) {
        size_t o = (size_t)(c0 + ty + 8 * j) * R + r0 + tx;
        T[o] = __float2half_rn(tile[tx][ty + 8 * j]);
    }
}

// ---------------------------------------------------------------------------
// Transpose fp32 -> fp16 hi/lo split (for w_o)
// ---------------------------------------------------------------------------
__global__ __launch_bounds__(256) void transpose_split_half_kernel(
    const float* __restrict__ W, int R, int C,
    __half* __restrict__ Th, __half* __restrict__ Tl) {
    __shared__ float tile[32][33];
    int r0 = blockIdx.y * 32, c0 = blockIdx.x * 32;
    int tx = threadIdx.x, ty = threadIdx.y;
#pragma unroll
    for (int j = 0; j < 4; j++)
        tile[ty + 8 * j][tx] = W[(size_t)(r0 + ty + 8 * j) * C + c0 + tx];
    __syncthreads();
#pragma unroll
    for (int j = 0; j < 4; j++) {
        float v = tile[tx][ty + 8 * j];
        __half hi = __float2half_rn(v);
        size_t o = (size_t)(c0 + ty + 8 * j) * R + r0 + tx;
        Th[o] = hi;
        Tl[o] = __float2half_rn(v - __half2float(hi));
    }
}

// ---------------------------------------------------------------------------
// h1 = LN1(AOproj[gather] + x) -> fp16 hi + fp16 lo (residual = hi+lo)
// ---------------------------------------------------------------------------
__global__ __launch_bounds__(256) void add_ln1_kernel(const float* __restrict__ x,
                                                      const float* __restrict__ w,
                                                      const float* __restrict__ b) {
    int ri = blockIdx.x;
    int n = ri >> 12, r = ri & 255;
    const float* pr = g_AOproj + ((size_t)((n << 8) | r)) * E_;
    const float* xr = x + (size_t)ri * E_;
    int t = threadIdx.x;
    float v[4]; float s = 0.f, s2 = 0.f;
#pragma unroll
    for (int i = 0; i < 4; i++) {
        int c = t + 256 * i;
        float u = pr[c] + xr[c];
        v[i] = u; s += u; s2 += u * u;
    }
    __shared__ float sh[2][8];
#pragma unroll
    for (int o = 16; o > 0; o >>= 1) {
        s  += __shfl_down_sync(0xFFFFFFFFu, s, o);
        s2 += __shfl_down_sync(0xFFFFFFFFu, s2, o);
    }
    int wid = t >> 5, lane = t & 31;
    if (lane == 0) { sh[0][wid] = s; sh[1][wid] = s2; }
    __syncthreads();
    if (t == 0) {
        float a = 0.f, c2 = 0.f;
#pragma unroll
        for (int i = 0; i < 8; i++) { a += sh[0][i]; c2 += sh[1][i]; }
        sh[0][0] = a; sh[1][0] = c2;
    }
    __syncthreads();
    float mean = sh[0][0] * (1.f / E_);
    float var  = sh[1][0] * (1.f / E_) - mean * mean;
    float rs   = rsqrtf(var + 1e-5f);
    __half* hrow = g_h1h + (size_t)ri * E_;
    __half* lrow = g_h1l + (size_t)ri * E_;
#pragma unroll
    for (int i = 0; i < 4; i++) {
        int c = t + 256 * i;
        float u = (v[i] - mean) * rs * w[c] + b[c];
        __half hi = __float2half_rn(u);
        hrow[c] = hi;
        lrow[c] = __float2half_rn(u - __half2float(hi));
    }
}

// ---------------------------------------------------------------------------
// Split-fp16 3-pass GEMM (w_o only): 64x64 block, 256 CTAs, occ 2.
// ---------------------------------------------------------------------------
__global__ __launch_bounds__(256, 2)
void wo_gemm_kernel(int M, int N, int K,
                    const __half* __restrict__ Ahi, const __half* __restrict__ Alo,
                    const __half* __restrict__ Bhi, const __half* __restrict__ Blo,
                    const float* __restrict__ bias, float* __restrict__ Cf) {
    constexpr uint32_t ST = 32768u;
    extern __shared__ char smem[];
    uint32_t sbase = smem_to_u32(smem);
    const int tid = threadIdx.x, lane = tid & 31, wid = tid >> 5;
    const int wm = wid & 1, wn = wid >> 1;

    const __half* Ah = Ahi + (size_t)blockIdx.y * 64 * K;
    const __half* Al = Alo + (size_t)blockIdx.y * 64 * K;
    const __half* Bh = Bhi + (size_t)blockIdx.x * 64 * K;
    const __half* Bl = Blo + (size_t)blockIdx.x * 64 * K;

    float acc[2][2][4] = {};

    const int la15 = lane & 15;
    const int khA  = lane >> 4;
    const int lbB  = (lane & 7) + ((lane & 16) >> 1);
    const int khB  = (lane >> 3) & 1;

    const int nc = K / 64;

    auto fill = [&](uint32_t stg, int k0) {
        const __half* srcs[4] = {Ah, Al, Bh, Bl};
#pragma unroll
        for (int s4 = 0; s4 < 4; s4++) {
            const __half* src = srcs[s4] + k0;
            uint32_t base = stg + s4 * 8192u;
#pragma unroll
            for (int j = 0; j < 2; j++) {
                int i = tid * 2 + j;
                int row = i >> 3, col = i & 7;
                CP_ASYNC16(base + SWZOFF(row, col), src + (size_t)row * K + col * 8);
            }
        }
    };

#pragma unroll
    for (int c = 0; c < 3; c++) { fill(sbase + c * ST, c * 64); CP_COMMIT(); }

    for (int c = 0; c < nc; c++) {
        int rem = nc - 1 - c;
        if (rem >= 2)      CP_WAIT(2);
        else if (rem == 1) CP_WAIT(1);
        else               CP_WAIT(0);
        __syncthreads();

        uint32_t st = sbase + (c % 3) * ST;
        uint32_t sA = st, sAl = st + 8192u, sB = st + 16384u, sBl = st + 24576u;

#pragma unroll
        for (int ks = 0; ks < 4; ks++) {
            uint32_t a_[2][4], bh_[2][2], bl_[2][2];
            int cA = ks * 2 + khA, cB = ks * 2 + khB;
#pragma unroll
            for (int mt = 0; mt < 2; mt++) {
                int r = wm * 32 + mt * 16 + la15;
                LDM_X4(a_[mt][0], a_[mt][1], a_[mt][2], a_[mt][3], sA + SWZOFF(r, cA));
            }
            {
                int r = wn * 16 + lbB;
                LDM_X4(bh_[0][0], bh_[0][1], bh_[1][0], bh_[1][1], sB + SWZOFF(r, cB));
                LDM_X4(bl_[0][0], bl_[0][1], bl_[1][0], bl_[1][1], sBl + SWZOFF(r, cB));
            }
#pragma unroll
            for (int mt = 0; mt < 2; mt++)
#pragma unroll
                for (int nt = 0; nt < 2; nt++) {
                    mma_fp16(acc[mt][nt], a_[mt], bh_[nt]);
                    mma_fp16(acc[mt][nt], a_[mt], bl_[nt]);
                }
#pragma unroll
            for (int mt = 0; mt < 2; mt++) {
                int r = wm * 32 + mt * 16 + la15;
                LDM_X4(a_[mt][0], a_[mt][1], a_[mt][2], a_[mt][3], sAl + SWZOFF(r, cA));
            }
#pragma unroll
            for (int mt = 0; mt < 2; mt++)
#pragma unroll
                for (int nt = 0; nt < 2; nt++)
                    mma_fp16(acc[mt][nt], a_[mt], bh_[nt]);
        }
        __syncthreads();

        if (c + 3 < nc) { fill(st, (c + 3) * 64); CP_COMMIT(); }
    }

    int rb = blockIdx.y * 64 + wm * 32 + (lane >> 2);
    int cb = blockIdx.x * 64 + wn * 16 + (lane & 3) * 2;
#pragma unroll
    for (int mt = 0; mt < 2; mt++)
#pragma unroll
        for (int h = 0; h < 2; h++) {
            size_t row = (size_t)rb + mt * 16 + h * 8;
#pragma unroll
            for (int nt = 0; nt < 2; nt++) {
                int col = cb + nt * 8;
                float2 o;
                o.x = acc[mt][nt][2 * h + 0] + bias[col];
                o.y = acc[mt][nt][2 * h + 1] + bias[col + 1];
                *reinterpret_cast<float2*>(Cf + row * N + col) = o;
            }
        }
}

// ---------------------------------------------------------------------------
// Shared FF mainloop body (identical math to R9): 128x128 block, 8 warps
// 64x32, BK=64, 3-stage cp.async, occ 2.
// EPI 1: relu(acc+bias) -> fp16 Ch    EPI 2: acc+bias+(addh+addl) -> fp32 Cf
// ---------------------------------------------------------------------------
template <int EPI>
__device__ __forceinline__ void ff_body(int bm, int bn, int N, int K,
                                        const __half* __restrict__ Aq,
                                        const __half* __restrict__ Bq,
                                        const float* __restrict__ bias,
                                        const __half* __restrict__ addh,
                                        const __half* __restrict__ addl,
                                        float* __restrict__ Cf,
                                        __half* __restrict__ Ch,
                                        uint32_t sbase, int tid) {
    constexpr uint32_t ST = 32768u;
    const int lane = tid & 31, wid = tid >> 5;
    const int wm = wid & 1, wn = wid >> 1;

    const __half* A = Aq + (size_t)bm * 128 * K;
    const __half* B = Bq + (size_t)bn * 128 * K;

    float acc[4][4][4] = {};

    const int la15 = lane & 15;
    const int khA  = lane >> 4;
    const int lbB  = (lane & 7) + ((lane & 16) >> 1);
    const int khB  = (lane >> 3) & 1;

    const int nc = K / 64;

    auto fill = [&](uint32_t stg, int k0) {
        const __half* srcs[2] = {A, B};
#pragma unroll
        for (int s2 = 0; s2 < 2; s2++) {
            const __half* src = srcs[s2] + k0;
            uint32_t base = stg + s2 * 16384u;
#pragma unroll
            for (int j = 0; j < 4; j++) {
                int i = tid * 4 + j;
                int row = i >> 3, col = i & 7;
                CP_ASYNC16(base + SWZOFF(row, col), src + (size_t)row * K + col * 8);
            }
        }
    };

#pragma unroll
    for (int c = 0; c < 3; c++) { fill(sbase + c * ST, c * 64); CP_COMMIT(); }

    for (int c = 0; c < nc; c++) {
        int rem = nc - 1 - c;
        if (rem >= 2)      CP_WAIT(2);
        else if (rem == 1) CP_WAIT(1);
        else               CP_WAIT(0);
        __syncthreads();

        uint32_t st = sbase + (c % 3) * ST;
        uint32_t sA = st, sB = st + 16384u;

#pragma unroll
        for (int ks = 0; ks < 4; ks++) {
            uint32_t a_[4][4], b_[4][2];
            int cA = ks * 2 + khA, cB = ks * 2 + khB;
#pragma unroll
            for (int mt = 0; mt < 4; mt++) {
                int r = wm * 64 + mt * 16 + la15;
                LDM_X4(a_[mt][0], a_[mt][1], a_[mt][2], a_[mt][3], sA + SWZOFF(r, cA));
            }
#pragma unroll
            for (int np = 0; np < 2; np++) {
                int r = wn * 32 + np * 16 + lbB;
                LDM_X4(b_[2 * np][0], b_[2 * np][1], b_[2 * np + 1][0], b_[2 * np + 1][1],
                       sB + SWZOFF(r, cB));
            }
#pragma unroll
            for (int mt = 0; mt < 4; mt++)
#pragma unroll
                for (int nt = 0; nt < 4; nt++)
                    mma_fp16(acc[mt][nt], a_[mt], b_[nt]);
        }
        __syncthreads();

        if (c + 3 < nc) { fill(st, (c + 3) * 64); CP_COMMIT(); }
    }

    int rb = bm * 128 + wm * 64 + (lane >> 2);
    int cb = bn * 128 + wn * 32 + (lane & 3) * 2;
#pragma unroll
    for (int mt = 0; mt < 4; mt++)
#pragma unroll
        for (int h = 0; h < 2; h++) {
            size_t row = (size_t)rb + mt * 16 + h * 8;
#pragma unroll
            for (int nt = 0; nt < 4; nt++) {
                int col = cb + nt * 8;
                float v0 = acc[mt][nt][2 * h + 0];
                float v1 = acc[mt][nt][2 * h + 1];
                if (EPI == 1) {
                    v0 = fmaxf(v0 + bias[col], 0.f);
                    v1 = fmaxf(v1 + bias[col + 1], 0.f);
                    __half2 p;
                    p.x = __float2half_rn(v0);
                    p.y = __float2half_rn(v1);
                    *reinterpret_cast<__half2*>(Ch + row * N + col) = p;
                } else {
                    __half2 ah = *reinterpret_cast<const __half2*>(addh + row * N + col);
                    __half2 al = *reinterpret_cast<const __half2*>(addl + row * N + col);
                    float2 o;
                    o.x = v0 + bias[col]     + __half2float(ah.x) + __half2float(al.x);
                    o.y = v1 + bias[col + 1] + __half2float(ah.y) + __half2float(al.y);
                    *reinterpret_cast<float2*>(Cf + row * N + col) = o;
                }
            }
        }
}

// ---------------------------------------------------------------------------
// Fused FF1+FF2: one grid of 4096+1024 CTAs.
// FF1 CTAs (bid < 4096, bid = m*32+n): t tile (m,n); after stores they
// fence + bump g_cnt[m]. FF2 CTAs wait for g_cnt[m]==32 (their t row-block
// fully written), then run. Dispatch is bid-monotone -> no deadlock.
// ---------------------------------------------------------------------------
__global__ __launch_bounds__(256, 2)
void fused_ff_kernel(const __half* __restrict__ wt1, const float* __restrict__ b_ff1,
                     const __half* __restrict__ wt2, const float* __restrict__ b_ff2,
                     float* __restrict__ out) {
    extern __shared__ char smem[];
    uint32_t sbase = smem_to_u32(smem);
    const int tid = threadIdx.x;
    const int bid = blockIdx.x;

    if (bid < 4096) {
        int m = bid >> 5, n = bid & 31;
        ff_body<1>(m, n, HID_, E_, g_h1h, wt1, b_ff1, nullptr, nullptr,
                   nullptr, g_t, sbase, tid);
        // publish: all stores visible, then bump row counter
        __threadfence();
        __syncthreads();
        if (tid == 0) atomicAdd(&g_cnt[m], 1);
    } else {
        int b2 = bid - 4096;
        int m = b2 >> 3, n = b2 & 7;
        if (tid == 0) {
            while (*((volatile int*)&g_cnt[m]) < 32) {}
        }
        __syncthreads();
        __threadfence();
        ff_body<2>(m, n, E_, HID_, g_t, wt2, b_ff2, g_h1h, g_h1l,
                   out, nullptr, sbase, tid);
    }
}

// ---------------------------------------------------------------------------
// LN2 in-place over d_out rows
// ---------------------------------------------------------------------------
__global__ __launch_bounds__(256) void ln2_inplace_kernel(float* __restrict__ z,
                                                          const float* __restrict__ w,
                                                          const float* __restrict__ b) {
    int ri = blockIdx.x;
    float* zr = z + (size_t)ri * E_;
    int t = threadIdx.x;
    float v[4]; float s = 0.f, s2 = 0.f;
#pragma unroll
    for (int i = 0; i < 4; i++) {
        int c = t + 256 * i;
        float u = zr[c];
        v[i] = u; s += u; s2 += u * u;
    }
    __shared__ float sh[2][8];
#pragma unroll
    for (int o = 16; o > 0; o >>= 1) {
        s  += __shfl_down_sync(0xFFFFFFFFu, s, o);
        s2 += __shfl_down_sync(0xFFFFFFFFu, s2, o);
    }
    int wid = t >> 5, lane = t & 31;
    if (lane == 0) { sh[0][wid] = s; sh[1][wid] = s2; }
    __syncthreads();
    if (t == 0) {
        float a = 0.f, c2 = 0.f;
#pragma unroll
        for (int i = 0; i < 8; i++) { a += sh[0][i]; c2 += sh[1][i]; }
        sh[0][0] = a; sh[1][0] = c2;
    }
    __syncthreads();
    float mean = sh[0][0] * (1.f / E_);
    float var  = sh[1][0] * (1.f / E_) - mean * mean;
    float rs   = rsqrtf(var + 1e-5f);
#pragma unroll
    for (int i = 0; i < 4; i++) {
        int c = t + 256 * i;
        zr[c] = (v[i] - mean) * rs * w[c] + b[c];
    }
}

// ---------------------------------------------------------------------------
// Launch
// ---------------------------------------------------------------------------
extern "C" void kernel_launch(void* const* d_in, const int* in_sizes, int n_in,
                              void* d_out, int out_size) {
    const float* x     = (const float*)d_in[0];
    const float* w_v   = (const float*)d_in[3];
    const float* w_o   = (const float*)d_in[4];
    const float* b_o   = (const float*)d_in[5];
    const float* ln1_w = (const float*)d_in[6];
    const float* ln1_b = (const float*)d_in[7];
    const float* ln2_w = (const float*)d_in[8];
    const float* ln2_b = (const float*)d_in[9];
    const float* w_ff1 = (const float*)d_in[10];
    const float* b_ff1 = (const float*)d_in[11];
    const float* w_ff2 = (const float*)d_in[12];
    const float* b_ff2 = (const float*)d_in[13];
    float* out = (float*)d_out;

    float* p_AOproj;
    __half *p_Sh, *p_Sl, *p_wtoh, *p_wtol, *p_wt1, *p_wt2;
    cudaGetSymbolAddress((void**)&p_AOproj, g_AOproj);
    cudaGetSymbolAddress((void**)&p_Sh, g_Sh);
    cudaGetSymbolAddress((void**)&p_Sl, g_Sl);
    cudaGetSymbolAddress((void**)&p_wtoh, g_wtoh);
    cudaGetSymbolAddress((void**)&p_wtol, g_wtol);
    cudaGetSymbolAddress((void**)&p_wt1, g_wt1);
    cudaGetSymbolAddress((void**)&p_wt2, g_wt2);

    cudaFuncSetAttribute(wo_gemm_kernel,  cudaFuncAttributeMaxDynamicSharedMemorySize, 3 * 32768);
    cudaFuncSetAttribute(fused_ff_kernel, cudaFuncAttributeMaxDynamicSharedMemorySize, 3 * 32768);

    // 0) wv_red; 1) S = x @ wv_red (fp16 split); 2) w_o transpose+split
    reduce_wv_kernel<<<E_, DH>>>(w_v);
    gemm_S_kernel<<<ROWS / 16, dim3(64, 4)>>>(x);
    transpose_split_half_kernel<<<dim3(E_ / 32, E_ / 32), dim3(32, 8)>>>(w_o, E_, E_, p_wtoh, p_wtol);

    // 3) AOproj = S(1024x1024) @ w_o + b_o   [ncu capture slot]
    wo_gemm_kernel<<<dim3(E_ / 64, E_ / 64), 256, 3 * 32768>>>(
        E_, E_, E_, p_Sh, p_Sl, p_wtoh, p_wtol, b_o, p_AOproj);

    // 4) reset producer counters; 5,6) FF weight transposes
    zero_cnt_kernel<<<1, ROWS / 128>>>();
    transpose_half_kernel<<<dim3(HID_ / 32, E_ / 32), dim3(32, 8)>>>(w_ff1, E_, HID_, p_wt1);
    transpose_half_kernel<<<dim3(E_ / 32, HID_ / 32), dim3(32, 8)>>>(w_ff2, HID_, E_, p_wt2);

    // 7) h1 = LN1(AOproj[gather] + x) -> fp16 hi/lo
    add_ln1_kernel<<<ROWS, 256>>>(x, ln1_w, ln1_b);

    // 8) fused FF1+FF2 (producer/consumer handshake, one wave train)
    fused_ff_kernel<<<4096 + 1024, 256, 3 * 32768>>>(p_wt1, b_ff1, p_wt2, b_ff2, out);

    // 9) LN2 in-place
    ln2_inplace_kernel<<<ROWS, 256>>>(out, ln2_w, ln2_b);
}

// round 11
// speedup vs baseline: 1.0118x; 1.0118x over previous
#include <cuda_runtime.h>
#include <cuda_fp16.h>
#include <cuda_bf16.h>
#include <cstdint>

// Shapes (fixed by the problem)
#define B_   4
#define L_   4096
#define E_   1024
#define HID_ 4096
#define ROWS (B_ * L_)        // 16384
#define DH   64               // head dim
#define HEADS_ 16

// ---------------------------------------------------------------------------
// PTX helpers (sm_103-safe: no tcgen05)
// ---------------------------------------------------------------------------
__device__ __forceinline__ uint32_t smem_to_u32(const void* p) {
    uint32_t a;
    asm("{ .reg .u64 t; cvta.to.shared.u64 t, %1; cvt.u32.u64 %0, t; }" : "=r"(a) : "l"(p));
    return a;
}
#define CP_ASYNC16(dst, src) asm volatile("cp.async.cg.shared.global [%0], [%1], 16;" :: "r"((uint32_t)(dst)), "l"(src) : "memory")
#define CP_COMMIT()          asm volatile("cp.async.commit_group;" ::: "memory")
#define CP_WAIT(N)           asm volatile("cp.async.wait_group %0;" :: "n"(N) : "memory")

#define LDM_X4(r0, r1, r2, r3, addr) \
    asm volatile("ldmatrix.sync.aligned.m8n8.x4.shared.b16 {%0,%1,%2,%3}, [%4];" \
        : "=r"(r0), "=r"(r1), "=r"(r2), "=r"(r3) : "r"(addr))

__device__ __forceinline__ void mma_fp16(float* c, const uint32_t* a, const uint32_t* b) {
    asm volatile("mma.sync.aligned.m16n8k16.row.col.f32.f16.f16.f32 "
        "{%0,%1,%2,%3}, {%4,%5,%6,%7}, {%8,%9}, {%0,%1,%2,%3};"
        : "+f"(c[0]), "+f"(c[1]), "+f"(c[2]), "+f"(c[3])
        : "r"(a[0]), "r"(a[1]), "r"(a[2]), "r"(a[3]), "r"(b[0]), "r"(b[1]));
}

// Rows are 128B wide; XOR 16B columns with (row & 7) -> conflict-free ldmatrix
#define SWZOFF(row, col16) (((uint32_t)(row) * 128u) + ((((uint32_t)(col16)) ^ ((uint32_t)(row) & 7u)) << 4))

// ---------------------------------------------------------------------------
// Scratch (device globals)
// ---------------------------------------------------------------------------
__device__ float g_wvred[E_ * DH];
__device__ __half g_Sh[E_ * E_];                   // S viewed as 1024x1024 (fp16)
__device__ float g_AOproj[B_ * 256 * E_];
__device__ __half g_h1h[(size_t)ROWS * E_];
__device__ __half g_h1l[(size_t)ROWS * E_];
__device__ __half g_t[(size_t)ROWS * HID_];
__device__ __half g_wto[(size_t)E_ * E_];
__device__ __half g_wt1[(size_t)HID_ * E_];
__device__ __half g_wt2[(size_t)HID_ * E_];

// ---------------------------------------------------------------------------
// wv_red[e,d] = sum_h w_v[e, h*64+d]
// ---------------------------------------------------------------------------
__global__ void reduce_wv_kernel(const float* __restrict__ w_v) {
    int e = blockIdx.x, d = threadIdx.x;
    const float* row = w_v + (size_t)e * E_;
    float s = 0.f;
#pragma unroll
    for (int h = 0; h < HEADS_; h++) s += row[h * DH + d];
    g_wvred[e * DH + d] = s;
}

// ---------------------------------------------------------------------------
// S = x @ wv_red  (16384 x 64, K=1024) -> fp16; 16 rows/block
// ---------------------------------------------------------------------------
__global__ __launch_bounds__(256) void gemm_S_kernel(const float* __restrict__ x) {
    int d = threadIdx.x;
    int mi = threadIdx.y;
    size_t m0 = (size_t)blockIdx.x * 16 + mi * 4;
    const float* xr0 = x + m0 * E_;
    const float* xr1 = xr0 + E_;
    const float* xr2 = xr1 + E_;
    const float* xr3 = xr2 + E_;
    float a0 = 0.f, a1 = 0.f, a2 = 0.f, a3 = 0.f;
#pragma unroll 4
    for (int k = 0; k < E_; k++) {
        float w = g_wvred[k * DH + d];
        a0 = fmaf(xr0[k], w, a0);
        a1 = fmaf(xr1[k], w, a1);
        a2 = fmaf(xr2[k], w, a2);
        a3 = fmaf(xr3[k], w, a3);
    }
    float av[4] = {a0, a1, a2, a3};
#pragma unroll
    for (int j = 0; j < 4; j++)
        g_Sh[(m0 + j) * DH + d] = __float2half_rn(av[j]);
}

// ---------------------------------------------------------------------------
// Transpose fp32 -> fp16 (single). T[c, r] = half(W[r, c])
// ---------------------------------------------------------------------------
__global__ __launch_bounds__(256) void transpose_half_kernel(
    const float* __restrict__ W, int R, int C, __half* __restrict__ T) {
    __shared__ float tile[32][33];
    int r0 = blockIdx.y * 32, c0 = blockIdx.x * 32;
    int tx = threadIdx.x, ty = threadIdx.y;
#pragma unroll
    for (int j = 0; j < 4; j++)
        tile[ty + 8 * j][tx] = W[(size_t)(r0 + ty + 8 * j) * C + c0 + tx];
    __syncthreads();
#pragma unroll
    for (int j = 0; j < 4; j++) {
        size_t o = (size_t)(c0 + ty + 8 * j) * R + r0 + tx;
        T[o] = __float2half_rn(tile[tx][ty + 8 * j]);
    }
}

// ---------------------------------------------------------------------------
// h1 = LN1(AOproj[gather] + x) -> fp16 hi + fp16 lo (residual = hi+lo)
// ---------------------------------------------------------------------------
__global__ __launch_bounds__(256) void add_ln1_kernel(const float* __restrict__ x,
                                                      const float* __restrict__ w,
                                                      const float* __restrict__ b) {
    int ri = blockIdx.x;
    int n = ri >> 12, r = ri & 255;
    const float* pr = g_AOproj + ((size_t)((n << 8) | r)) * E_;
    const float* xr = x + (size_t)ri * E_;
    int t = threadIdx.x;
    float v[4]; float s = 0.f, s2 = 0.f;
#pragma unroll
    for (int i = 0; i < 4; i++) {
        int c = t + 256 * i;
        float u = pr[c] + xr[c];
        v[i] = u; s += u; s2 += u * u;
    }
    __shared__ float sh[2][8];
#pragma unroll
    for (int o = 16; o > 0; o >>= 1) {
        s  += __shfl_down_sync(0xFFFFFFFFu, s, o);
        s2 += __shfl_down_sync(0xFFFFFFFFu, s2, o);
    }
    int wid = t >> 5, lane = t & 31;
    if (lane == 0) { sh[0][wid] = s; sh[1][wid] = s2; }
    __syncthreads();
    if (t == 0) {
        float a = 0.f, c2 = 0.f;
#pragma unroll
        for (int i = 0; i < 8; i++) { a += sh[0][i]; c2 += sh[1][i]; }
        sh[0][0] = a; sh[1][0] = c2;
    }
    __syncthreads();
    float mean = sh[0][0] * (1.f / E_);
    float var  = sh[1][0] * (1.f / E_) - mean * mean;
    float rs   = rsqrtf(var + 1e-5f);
    __half* hrow = g_h1h + (size_t)ri * E_;
    __half* lrow = g_h1l + (size_t)ri * E_;
#pragma unroll
    for (int i = 0; i < 4; i++) {
        int c = t + 256 * i;
        float u = (v[i] - mean) * rs * w[c] + b[c];
        __half hi = __float2half_rn(u);
        hrow[c] = hi;
        lrow[c] = __float2half_rn(u - __half2float(hi));
    }
}

// ---------------------------------------------------------------------------
// 1-pass fp16 GEMM (w_o): 64x64 block, 256 CTAs, occ 2.
// 8 warps as 2x4 (warp tile 32x16).  acc + bias -> fp32 Cf.
// Stage: A 8K | B 8K = 16KB.
// ---------------------------------------------------------------------------
__global__ __launch_bounds__(256, 2)
void wo_gemm_kernel(int M, int N, int K,
                    const __half* __restrict__ Aq, const __half* __restrict__ Bq,
                    const float* __restrict__ bias, float* __restrict__ Cf) {
    constexpr uint32_t ST = 16384u;
    extern __shared__ char smem[];
    uint32_t sbase = smem_to_u32(smem);
    const int tid = threadIdx.x, lane = tid & 31, wid = tid >> 5;
    const int wm = wid & 1, wn = wid >> 1;   // warp tile 32x16 at (wm*32, wn*16)

    const __half* A = Aq + (size_t)blockIdx.y * 64 * K;
    const __half* B = Bq + (size_t)blockIdx.x * 64 * K;

    float acc[2][2][4] = {};

    const int la15 = lane & 15;
    const int khA  = lane >> 4;
    const int lbB  = (lane & 7) + ((lane & 16) >> 1);
    const int khB  = (lane >> 3) & 1;

    const int nc = K / 64;

    auto fill = [&](uint32_t stg, int k0) {
        const __half* srcs[2] = {A, B};
#pragma unroll
        for (int s2 = 0; s2 < 2; s2++) {
            const __half* src = srcs[s2] + k0;
            uint32_t base = stg + s2 * 8192u;
#pragma unroll
            for (int j = 0; j < 2; j++) {
                int i = tid * 2 + j;
                int row = i >> 3, col = i & 7;
                CP_ASYNC16(base + SWZOFF(row, col), src + (size_t)row * K + col * 8);
            }
        }
    };

#pragma unroll
    for (int c = 0; c < 3; c++) { fill(sbase + c * ST, c * 64); CP_COMMIT(); }

    for (int c = 0; c < nc; c++) {
        int rem = nc - 1 - c;
        if (rem >= 2)      CP_WAIT(2);
        else if (rem == 1) CP_WAIT(1);
        else               CP_WAIT(0);
        __syncthreads();

        uint32_t st = sbase + (c % 3) * ST;
        uint32_t sA = st, sB = st + 8192u;

#pragma unroll
        for (int ks = 0; ks < 4; ks++) {
            uint32_t a_[2][4], b_[2][2];
            int cA = ks * 2 + khA, cB = ks * 2 + khB;
#pragma unroll
            for (int mt = 0; mt < 2; mt++) {
                int r = wm * 32 + mt * 16 + la15;
                LDM_X4(a_[mt][0], a_[mt][1], a_[mt][2], a_[mt][3], sA + SWZOFF(r, cA));
            }
            {
                int r = wn * 16 + lbB;
                LDM_X4(b_[0][0], b_[0][1], b_[1][0], b_[1][1], sB + SWZOFF(r, cB));
            }
#pragma unroll
            for (int mt = 0; mt < 2; mt++)
#pragma unroll
                for (int nt = 0; nt < 2; nt++)
                    mma_fp16(acc[mt][nt], a_[mt], b_[nt]);
        }
        __syncthreads();

        if (c + 3 < nc) { fill(st, (c + 3) * 64); CP_COMMIT(); }
    }

    int rb = blockIdx.y * 64 + wm * 32 + (lane >> 2);
    int cb = blockIdx.x * 64 + wn * 16 + (lane & 3) * 2;
#pragma unroll
    for (int mt = 0; mt < 2; mt++)
#pragma unroll
        for (int h = 0; h < 2; h++) {
            size_t row = (size_t)rb + mt * 16 + h * 8;
#pragma unroll
            for (int nt = 0; nt < 2; nt++) {
                int col = cb + nt * 8;
                float2 o;
                o.x = acc[mt][nt][2 * h + 0] + bias[col];
                o.y = acc[mt][nt][2 * h + 1] + bias[col + 1];
                *reinterpret_cast<float2*>(Cf + row * N + col) = o;
            }
        }
}

// ---------------------------------------------------------------------------
// FF GEMM: 1-pass fp16, 128x128 block, 8 warps 64x32, BK=64, occ 2.
// EPI 1: relu(acc+bias) -> fp16 Ch
// EPI 2: acc + bias + (addh+addl) -> fp32 Cf
// Stage: [A 16K | B 16K] = 32KB.
// ---------------------------------------------------------------------------
template <int EPI>
__global__ __launch_bounds__(256, 2)
void ff_gemm_kernel(int M, int N, int K,
                    const __half* __restrict__ Aq, const __half* __restrict__ Bq,
                    const float* __restrict__ bias,
                    const __half* __restrict__ addh, const __half* __restrict__ addl,
                    float* __restrict__ Cf, __half* __restrict__ Ch) {
    constexpr uint32_t ST = 32768u;
    extern __shared__ char smem[];
    uint32_t sbase = smem_to_u32(smem);
    const int tid = threadIdx.x, lane = tid & 31, wid = tid >> 5;
    const int wm = wid & 1, wn = wid >> 1;

    const __half* A = Aq + (size_t)blockIdx.y * 128 * K;
    const __half* B = Bq + (size_t)blockIdx.x * 128 * K;

    float acc[4][4][4] = {};

    const int la15 = lane & 15;
    const int khA  = lane >> 4;
    const int lbB  = (lane & 7) + ((lane & 16) >> 1);
    const int khB  = (lane >> 3) & 1;

    const int nc = K / 64;

    auto fill = [&](uint32_t stg, int k0) {
        const __half* srcs[2] = {A, B};
#pragma unroll
        for (int s2 = 0; s2 < 2; s2++) {
            const __half* src = srcs[s2] + k0;
            uint32_t base = stg + s2 * 16384u;
#pragma unroll
            for (int j = 0; j < 4; j++) {
                int i = tid * 4 + j;
                int row = i >> 3, col = i & 7;
                CP_ASYNC16(base + SWZOFF(row, col), src + (size_t)row * K + col * 8);
            }
        }
    };

#pragma unroll
    for (int c = 0; c < 3; c++) { fill(sbase + c * ST, c * 64); CP_COMMIT(); }

    for (int c = 0; c < nc; c++) {
        int rem = nc - 1 - c;
        if (rem >= 2)      CP_WAIT(2);
        else if (rem == 1) CP_WAIT(1);
        else               CP_WAIT(0);
        __syncthreads();

        uint32_t st = sbase + (c % 3) * ST;
        uint32_t sA = st, sB = st + 16384u;

#pragma unroll
        for (int ks = 0; ks < 4; ks++) {
            uint32_t a_[4][4], b_[4][2];
            int cA = ks * 2 + khA, cB = ks * 2 + khB;
#pragma unroll
            for (int mt = 0; mt < 4; mt++) {
                int r = wm * 64 + mt * 16 + la15;
                LDM_X4(a_[mt][0], a_[mt][1], a_[mt][2], a_[mt][3], sA + SWZOFF(r, cA));
            }
#pragma unroll
            for (int np = 0; np < 2; np++) {
                int r = wn * 32 + np * 16 + lbB;
                LDM_X4(b_[2 * np][0], b_[2 * np][1], b_[2 * np + 1][0], b_[2 * np + 1][1],
                       sB + SWZOFF(r, cB));
            }
#pragma unroll
            for (int mt = 0; mt < 4; mt++)
#pragma unroll
                for (int nt = 0; nt < 4; nt++)
                    mma_fp16(acc[mt][nt], a_[mt], b_[nt]);
        }
        __syncthreads();

        if (c + 3 < nc) { fill(st, (c + 3) * 64); CP_COMMIT(); }
    }

    int rb = blockIdx.y * 128 + wm * 64 + (lane >> 2);
    int cb = blockIdx.x * 128 + wn * 32 + (lane & 3) * 2;
#pragma unroll
    for (int mt = 0; mt < 4; mt++)
#pragma unroll
        for (int h = 0; h < 2; h++) {
            size_t row = (size_t)rb + mt * 16 + h * 8;
#pragma unroll
            for (int nt = 0; nt < 4; nt++) {
                int col = cb + nt * 8;
                float v0 = acc[mt][nt][2 * h + 0];
                float v1 = acc[mt][nt][2 * h + 1];
                if (EPI == 1) {
                    v0 = fmaxf(v0 + bias[col], 0.f);
                    v1 = fmaxf(v1 + bias[col + 1], 0.f);
                    __half2 p;
                    p.x = __float2half_rn(v0);
                    p.y = __float2half_rn(v1);
                    *reinterpret_cast<__half2*>(Ch + row * N + col) = p;
                } else {
                    __half2 ah = *reinterpret_cast<const __half2*>(addh + row * N + col);
                    __half2 al = *reinterpret_cast<const __half2*>(addl + row * N + col);
                    float2 o;
                    o.x = v0 + bias[col]     + __half2float(ah.x) + __half2float(al.x);
                    o.y = v1 + bias[col + 1] + __half2float(ah.y) + __half2float(al.y);
                    *reinterpret_cast<float2*>(Cf + row * N + col) = o;
                }
            }
        }
}

// ---------------------------------------------------------------------------
// LN2 in-place over d_out rows
// ---------------------------------------------------------------------------
__global__ __launch_bounds__(256) void ln2_inplace_kernel(float* __restrict__ z,
                                                          const float* __restrict__ w,
                                                          const float* __restrict__ b) {
    int ri = blockIdx.x;
    float* zr = z + (size_t)ri * E_;
    int t = threadIdx.x;
    float v[4]; float s = 0.f, s2 = 0.f;
#pragma unroll
    for (int i = 0; i < 4; i++) {
        int c = t + 256 * i;
        float u = zr[c];
        v[i] = u; s += u; s2 += u * u;
    }
    __shared__ float sh[2][8];
#pragma unroll
    for (int o = 16; o > 0; o >>= 1) {
        s  += __shfl_down_sync(0xFFFFFFFFu, s, o);
        s2 += __shfl_down_sync(0xFFFFFFFFu, s2, o);
    }
    int wid = t >> 5, lane = t & 31;
    if (lane == 0) { sh[0][wid] = s; sh[1][wid] = s2; }
    __syncthreads();
    if (t == 0) {
        float a = 0.f, c2 = 0.f;
#pragma unroll
        for (int i = 0; i < 8; i++) { a += sh[0][i]; c2 += sh[1][i]; }
        sh[0][0] = a; sh[1][0] = c2;
    }
    __syncthreads();
    float mean = sh[0][0] * (1.f / E_);
    float var  = sh[1][0] * (1.f / E_) - mean * mean;
    float rs   = rsqrtf(var + 1e-5f);
#pragma unroll
    for (int i = 0; i < 4; i++) {
        int c = t + 256 * i;
        zr[c] = (v[i] - mean) * rs * w[c] + b[c];
    }
}

// ---------------------------------------------------------------------------
// Launch
// ---------------------------------------------------------------------------
extern "C" void kernel_launch(void* const* d_in, const int* in_sizes, int n_in,
                              void* d_out, int out_size) {
    const float* x     = (const float*)d_in[0];
    const float* w_v   = (const float*)d_in[3];
    const float* w_o   = (const float*)d_in[4];
    const float* b_o   = (const float*)d_in[5];
    const float* ln1_w = (const float*)d_in[6];
    const float* ln1_b = (const float*)d_in[7];
    const float* ln2_w = (const float*)d_in[8];
    const float* ln2_b = (const float*)d_in[9];
    const float* w_ff1 = (const float*)d_in[10];
    const float* b_ff1 = (const float*)d_in[11];
    const float* w_ff2 = (const float*)d_in[12];
    const float* b_ff2 = (const float*)d_in[13];
    float* out = (float*)d_out;

    float* p_AOproj;
    __half *p_Sh, *p_h1h, *p_h1l, *p_t, *p_wto, *p_wt1, *p_wt2;
    cudaGetSymbolAddress((void**)&p_AOproj, g_AOproj);
    cudaGetSymbolAddress((void**)&p_Sh, g_Sh);
    cudaGetSymbolAddress((void**)&p_h1h, g_h1h);
    cudaGetSymbolAddress((void**)&p_h1l, g_h1l);
    cudaGetSymbolAddress((void**)&p_t, g_t);
    cudaGetSymbolAddress((void**)&p_wto, g_wto);
    cudaGetSymbolAddress((void**)&p_wt1, g_wt1);
    cudaGetSymbolAddress((void**)&p_wt2, g_wt2);

    cudaFuncSetAttribute(wo_gemm_kernel,    cudaFuncAttributeMaxDynamicSharedMemorySize, 3 * 16384);
    cudaFuncSetAttribute(ff_gemm_kernel<1>, cudaFuncAttributeMaxDynamicSharedMemorySize, 3 * 32768);
    cudaFuncSetAttribute(ff_gemm_kernel<2>, cudaFuncAttributeMaxDynamicSharedMemorySize, 3 * 32768);

    // 0) wv_red; 1) S = x @ wv_red (fp16); 2) w_o transpose
    reduce_wv_kernel<<<E_, DH>>>(w_v);
    gemm_S_kernel<<<ROWS / 16, dim3(64, 4)>>>(x);
    transpose_half_kernel<<<dim3(E_ / 32, E_ / 32), dim3(32, 8)>>>(w_o, E_, E_, p_wto);

    // 3) AOproj = S(1024x1024) @ w_o + b_o   (1-pass fp16) [ncu capture slot]
    wo_gemm_kernel<<<dim3(E_ / 64, E_ / 64), 256, 3 * 16384>>>(
        E_, E_, E_, p_Sh, p_wto, b_o, p_AOproj);

    // 4,5) FF weight transposes
    transpose_half_kernel<<<dim3(HID_ / 32, E_ / 32), dim3(32, 8)>>>(w_ff1, E_, HID_, p_wt1);
    transpose_half_kernel<<<dim3(E_ / 32, HID_ / 32), dim3(32, 8)>>>(w_ff2, HID_, E_, p_wt2);

    // 6) h1 = LN1(AOproj[gather] + x) -> fp16 hi/lo
    add_ln1_kernel<<<ROWS, 256>>>(x, ln1_w, ln1_b);

    // 7) t = relu(h1 @ w_ff1 + b_ff1) -> fp16   (128x128, occ 2)
    ff_gemm_kernel<1><<<dim3(HID_ / 128, ROWS / 128), 256, 3 * 32768>>>(
        ROWS, HID_, E_, p_h1h, p_wt1, b_ff1, nullptr, nullptr, nullptr, p_t);

    // 8) out = t @ w_ff2 + b_ff2 + h1   (128x128, occ 2)
    ff_gemm_kernel<2><<<dim3(E_ / 128, ROWS / 128), 256, 3 * 32768>>>(
        ROWS, E_, HID_, p_t, p_wt2, b_ff2, p_h1h, p_h1l, out, nullptr);

    // 9) LN2 in-place
    ln2_inplace_kernel<<<ROWS, 256>>>(out, ln2_w, ln2_b);
}

// round 12
// speedup vs baseline: 1.0129x; 1.0012x over previous
#include <cuda_runtime.h>
#include <cuda_fp16.h>
#include <cuda_bf16.h>
#include <cstdint>

// Shapes (fixed by the problem)
#define B_   4
#define L_   4096
#define E_   1024
#define HID_ 4096
#define ROWS (B_ * L_)        // 16384
#define DH   64               // head dim
#define HEADS_ 16

// ---------------------------------------------------------------------------
// PTX helpers (sm_103-safe: no tcgen05)
// ---------------------------------------------------------------------------
__device__ __forceinline__ uint32_t smem_to_u32(const void* p) {
    uint32_t a;
    asm("{ .reg .u64 t; cvta.to.shared.u64 t, %1; cvt.u32.u64 %0, t; }" : "=r"(a) : "l"(p));
    return a;
}
#define CP_ASYNC16(dst, src) asm volatile("cp.async.cg.shared.global [%0], [%1], 16;" :: "r"((uint32_t)(dst)), "l"(src) : "memory")
#define CP_COMMIT()          asm volatile("cp.async.commit_group;" ::: "memory")
#define CP_WAIT(N)           asm volatile("cp.async.wait_group %0;" :: "n"(N) : "memory")

#define LDM_X4(r0, r1, r2, r3, addr) \
    asm volatile("ldmatrix.sync.aligned.m8n8.x4.shared.b16 {%0,%1,%2,%3}, [%4];" \
        : "=r"(r0), "=r"(r1), "=r"(r2), "=r"(r3) : "r"(addr))

__device__ __forceinline__ void mma_fp16(float* c, const uint32_t* a, const uint32_t* b) {
    asm volatile("mma.sync.aligned.m16n8k16.row.col.f32.f16.f16.f32 "
        "{%0,%1,%2,%3}, {%4,%5,%6,%7}, {%8,%9}, {%0,%1,%2,%3};"
        : "+f"(c[0]), "+f"(c[1]), "+f"(c[2]), "+f"(c[3])
        : "r"(a[0]), "r"(a[1]), "r"(a[2]), "r"(a[3]), "r"(b[0]), "r"(b[1]));
}

// Rows are 128B wide; XOR 16B columns with (row & 7) -> conflict-free ldmatrix
#define SWZOFF(row, col16) (((uint32_t)(row) * 128u) + ((((uint32_t)(col16)) ^ ((uint32_t)(row) & 7u)) << 4))

// ---------------------------------------------------------------------------
// Scratch (device globals)
// ---------------------------------------------------------------------------
__device__ float g_wvred[E_ * DH];
__device__ __half g_Sh[E_ * E_];                   // S viewed as 1024x1024 (fp16)
__device__ float g_AOproj[B_ * 256 * E_];
__device__ __half g_h1h[(size_t)ROWS * E_];
__device__ __half g_h1l[(size_t)ROWS * E_];
__device__ __half g_t[(size_t)ROWS * HID_];
__device__ __half g_wto[(size_t)E_ * E_];
__device__ __half g_wt1[(size_t)HID_ * E_];
__device__ __half g_wt2[(size_t)HID_ * E_];

// ---------------------------------------------------------------------------
// wv_red[e,d] = sum_h w_v[e, h*64+d]
// ---------------------------------------------------------------------------
__global__ void reduce_wv_kernel(const float* __restrict__ w_v) {
    int e = blockIdx.x, d = threadIdx.x;
    const float* row = w_v + (size_t)e * E_;
    float s = 0.f;
#pragma unroll
    for (int h = 0; h < HEADS_; h++) s += row[h * DH + d];
    g_wvred[e * DH + d] = s;
}

// ---------------------------------------------------------------------------
// S = x @ wv_red  (16384 x 64, K=1024) -> fp16; 16 rows/block
// ---------------------------------------------------------------------------
__global__ __launch_bounds__(256) void gemm_S_kernel(const float* __restrict__ x) {
    int d = threadIdx.x;
    int mi = threadIdx.y;
    size_t m0 = (size_t)blockIdx.x * 16 + mi * 4;
    const float* xr0 = x + m0 * E_;
    const float* xr1 = xr0 + E_;
    const float* xr2 = xr1 + E_;
    const float* xr3 = xr2 + E_;
    float a0 = 0.f, a1 = 0.f, a2 = 0.f, a3 = 0.f;
#pragma unroll 4
    for (int k = 0; k < E_; k++) {
        float w = g_wvred[k * DH + d];
        a0 = fmaf(xr0[k], w, a0);
        a1 = fmaf(xr1[k], w, a1);
        a2 = fmaf(xr2[k], w, a2);
        a3 = fmaf(xr3[k], w, a3);
    }
    float av[4] = {a0, a1, a2, a3};
#pragma unroll
    for (int j = 0; j < 4; j++)
        g_Sh[(m0 + j) * DH + d] = __float2half_rn(av[j]);
}

// ---------------------------------------------------------------------------
// Transpose fp32 -> fp16 (single). T[c, r] = half(W[r, c])
// ---------------------------------------------------------------------------
__global__ __launch_bounds__(256) void transpose_half_kernel(
    const float* __restrict__ W, int R, int C, __half* __restrict__ T) {
    __shared__ float tile[32][33];
    int r0 = blockIdx.y * 32, c0 = blockIdx.x * 32;
    int tx = threadIdx.x, ty = threadIdx.y;
#pragma unroll
    for (int j = 0; j < 4; j++)
        tile[ty + 8 * j][tx] = W[(size_t)(r0 + ty + 8 * j) * C + c0 + tx];
    __syncthreads();
#pragma unroll
    for (int j = 0; j < 4; j++) {
        size_t o = (size_t)(c0 + ty + 8 * j) * R + r0 + tx;
        T[o] = __float2half_rn(tile[tx][ty + 8 * j]);
    }
}

// ---------------------------------------------------------------------------
// h1 = LN1(AOproj[gather] + x) -> fp16 hi + fp16 lo (residual = hi+lo)
// ---------------------------------------------------------------------------
__global__ __launch_bounds__(256) void add_ln1_kernel(const float* __restrict__ x,
                                                      const float* __restrict__ w,
                                                      const float* __restrict__ b) {
    int ri = blockIdx.x;
    int n = ri >> 12, r = ri & 255;
    const float* pr = g_AOproj + ((size_t)((n << 8) | r)) * E_;
    const float* xr = x + (size_t)ri * E_;
    int t = threadIdx.x;
    float v[4]; float s = 0.f, s2 = 0.f;
#pragma unroll
    for (int i = 0; i < 4; i++) {
        int c = t + 256 * i;
        float u = pr[c] + xr[c];
        v[i] = u; s += u; s2 += u * u;
    }
    __shared__ float sh[2][8];
#pragma unroll
    for (int o = 16; o > 0; o >>= 1) {
        s  += __shfl_down_sync(0xFFFFFFFFu, s, o);
        s2 += __shfl_down_sync(0xFFFFFFFFu, s2, o);
    }
    int wid = t >> 5, lane = t & 31;
    if (lane == 0) { sh[0][wid] = s; sh[1][wid] = s2; }
    __syncthreads();
    if (t == 0) {
        float a = 0.f, c2 = 0.f;
#pragma unroll
        for (int i = 0; i < 8; i++) { a += sh[0][i]; c2 += sh[1][i]; }
        sh[0][0] = a; sh[1][0] = c2;
    }
    __syncthreads();
    float mean = sh[0][0] * (1.f / E_);
    float var  = sh[1][0] * (1.f / E_) - mean * mean;
    float rs   = rsqrtf(var + 1e-5f);
    __half* hrow = g_h1h + (size_t)ri * E_;
    __half* lrow = g_h1l + (size_t)ri * E_;
#pragma unroll
    for (int i = 0; i < 4; i++) {
        int c = t + 256 * i;
        float u = (v[i] - mean) * rs * w[c] + b[c];
        __half hi = __float2half_rn(u);
        hrow[c] = hi;
        lrow[c] = __float2half_rn(u - __half2float(hi));
    }
}

// ---------------------------------------------------------------------------
// 1-pass fp16 GEMM (w_o): 64x64 block, 256 CTAs, occ 2.
// ---------------------------------------------------------------------------
__global__ __launch_bounds__(256, 2)
void wo_gemm_kernel(int M, int N, int K,
                    const __half* __restrict__ Aq, const __half* __restrict__ Bq,
                    const float* __restrict__ bias, float* __restrict__ Cf) {
    constexpr uint32_t ST = 16384u;
    extern __shared__ char smem[];
    uint32_t sbase = smem_to_u32(smem);
    const int tid = threadIdx.x, lane = tid & 31, wid = tid >> 5;
    const int wm = wid & 1, wn = wid >> 1;   // warp tile 32x16

    const __half* A = Aq + (size_t)blockIdx.y * 64 * K;
    const __half* B = Bq + (size_t)blockIdx.x * 64 * K;

    float acc[2][2][4] = {};

    const int la15 = lane & 15;
    const int khA  = lane >> 4;
    const int lbB  = (lane & 7) + ((lane & 16) >> 1);
    const int khB  = (lane >> 3) & 1;

    const int nc = K / 64;

    auto fill = [&](uint32_t stg, int k0) {
        const __half* srcs[2] = {A, B};
#pragma unroll
        for (int s2 = 0; s2 < 2; s2++) {
            const __half* src = srcs[s2] + k0;
            uint32_t base = stg + s2 * 8192u;
#pragma unroll
            for (int j = 0; j < 2; j++) {
                int i = tid * 2 + j;
                int row = i >> 3, col = i & 7;
                CP_ASYNC16(base + SWZOFF(row, col), src + (size_t)row * K + col * 8);
            }
        }
    };

#pragma unroll
    for (int c = 0; c < 3; c++) { fill(sbase + c * ST, c * 64); CP_COMMIT(); }

    for (int c = 0; c < nc; c++) {
        int rem = nc - 1 - c;
        if (rem >= 2)      CP_WAIT(2);
        else if (rem == 1) CP_WAIT(1);
        else               CP_WAIT(0);
        __syncthreads();

        uint32_t st = sbase + (c % 3) * ST;
        uint32_t sA = st, sB = st + 8192u;

#pragma unroll
        for (int ks = 0; ks < 4; ks++) {
            uint32_t a_[2][4], b_[2][2];
            int cA = ks * 2 + khA, cB = ks * 2 + khB;
#pragma unroll
            for (int mt = 0; mt < 2; mt++) {
                int r = wm * 32 + mt * 16 + la15;
                LDM_X4(a_[mt][0], a_[mt][1], a_[mt][2], a_[mt][3], sA + SWZOFF(r, cA));
            }
            {
                int r = wn * 16 + lbB;
                LDM_X4(b_[0][0], b_[0][1], b_[1][0], b_[1][1], sB + SWZOFF(r, cB));
            }
#pragma unroll
            for (int mt = 0; mt < 2; mt++)
#pragma unroll
                for (int nt = 0; nt < 2; nt++)
                    mma_fp16(acc[mt][nt], a_[mt], b_[nt]);
        }
        __syncthreads();

        if (c + 3 < nc) { fill(st, (c + 3) * 64); CP_COMMIT(); }
    }

    int rb = blockIdx.y * 64 + wm * 32 + (lane >> 2);
    int cb = blockIdx.x * 64 + wn * 16 + (lane & 3) * 2;
#pragma unroll
    for (int mt = 0; mt < 2; mt++)
#pragma unroll
        for (int h = 0; h < 2; h++) {
            size_t row = (size_t)rb + mt * 16 + h * 8;
#pragma unroll
            for (int nt = 0; nt < 2; nt++) {
                int col = cb + nt * 8;
                float2 o;
                o.x = acc[mt][nt][2 * h + 0] + bias[col];
                o.y = acc[mt][nt][2 * h + 1] + bias[col + 1];
                *reinterpret_cast<float2*>(Cf + row * N + col) = o;
            }
        }
}

// ---------------------------------------------------------------------------
// FF GEMM: 1-pass fp16, 128x128 block, 8 warps 64x32, BK=64, occ 2.
// A-fragments double-buffered across ks-steps (overlap ldmatrix with HMMA).
// EPI 1: relu(acc+bias) -> fp16 Ch
// EPI 2: acc + bias + (addh+addl) -> fp32 Cf
// ---------------------------------------------------------------------------
template <int EPI>
__global__ __launch_bounds__(256, 2)
void ff_gemm_kernel(int M, int N, int K,
                    const __half* __restrict__ Aq, const __half* __restrict__ Bq,
                    const float* __restrict__ bias,
                    const __half* __restrict__ addh, const __half* __restrict__ addl,
                    float* __restrict__ Cf, __half* __restrict__ Ch) {
    constexpr uint32_t ST = 32768u;
    extern __shared__ char smem[];
    uint32_t sbase = smem_to_u32(smem);
    const int tid = threadIdx.x, lane = tid & 31, wid = tid >> 5;
    const int wm = wid & 1, wn = wid >> 1;

    const __half* A = Aq + (size_t)blockIdx.y * 128 * K;
    const __half* B = Bq + (size_t)blockIdx.x * 128 * K;

    float acc[4][4][4] = {};

    const int la15 = lane & 15;
    const int khA  = lane >> 4;
    const int lbB  = (lane & 7) + ((lane & 16) >> 1);
    const int khB  = (lane >> 3) & 1;

    const int nc = K / 64;

    auto fill = [&](uint32_t stg, int k0) {
        const __half* srcs[2] = {A, B};
#pragma unroll
        for (int s2 = 0; s2 < 2; s2++) {
            const __half* src = srcs[s2] + k0;
            uint32_t base = stg + s2 * 16384u;
#pragma unroll
            for (int j = 0; j < 4; j++) {
                int i = tid * 4 + j;
                int row = i >> 3, col = i & 7;
                CP_ASYNC16(base + SWZOFF(row, col), src + (size_t)row * K + col * 8);
            }
        }
    };

#pragma unroll
    for (int c = 0; c < 3; c++) { fill(sbase + c * ST, c * 64); CP_COMMIT(); }

    for (int c = 0; c < nc; c++) {
        int rem = nc - 1 - c;
        if (rem >= 2)      CP_WAIT(2);
        else if (rem == 1) CP_WAIT(1);
        else               CP_WAIT(0);
        __syncthreads();

        uint32_t st = sbase + (c % 3) * ST;
        uint32_t sA = st, sB = st + 16384u;

        // A-fragment double buffer: load ks=0 set, then prefetch ks+1
        uint32_t a_[2][4][4], b_[4][2];
#pragma unroll
        for (int mt = 0; mt < 4; mt++) {
            int r = wm * 64 + mt * 16 + la15;
            LDM_X4(a_[0][mt][0], a_[0][mt][1], a_[0][mt][2], a_[0][mt][3],
                   sA + SWZOFF(r, khA));
        }

#pragma unroll
        for (int ks = 0; ks < 4; ks++) {
            const int cur = ks & 1, nxt = cur ^ 1;
            int cB = ks * 2 + khB;
            // B fragments for this ks
#pragma unroll
            for (int np = 0; np < 2; np++) {
                int r = wn * 32 + np * 16 + lbB;
                LDM_X4(b_[2 * np][0], b_[2 * np][1], b_[2 * np + 1][0], b_[2 * np + 1][1],
                       sB + SWZOFF(r, cB));
            }
            // prefetch next ks's A fragments while MMAs below execute
            if (ks < 3) {
                int cA = (ks + 1) * 2 + khA;
#pragma unroll
                for (int mt = 0; mt < 4; mt++) {
                    int r = wm * 64 + mt * 16 + la15;
                    LDM_X4(a_[nxt][mt][0], a_[nxt][mt][1], a_[nxt][mt][2], a_[nxt][mt][3],
                           sA + SWZOFF(r, cA));
                }
            }
#pragma unroll
            for (int mt = 0; mt < 4; mt++)
#pragma unroll
                for (int nt = 0; nt < 4; nt++)
                    mma_fp16(acc[mt][nt], a_[cur][mt], b_[nt]);
        }
        __syncthreads();

        if (c + 3 < nc) { fill(st, (c + 3) * 64); CP_COMMIT(); }
    }

    int rb = blockIdx.y * 128 + wm * 64 + (lane >> 2);
    int cb = blockIdx.x * 128 + wn * 32 + (lane & 3) * 2;
#pragma unroll
    for (int mt = 0; mt < 4; mt++)
#pragma unroll
        for (int h = 0; h < 2; h++) {
            size_t row = (size_t)rb + mt * 16 + h * 8;
#pragma unroll
            for (int nt = 0; nt < 4; nt++) {
                int col = cb + nt * 8;
                float v0 = acc[mt][nt][2 * h + 0];
                float v1 = acc[mt][nt][2 * h + 1];
                if (EPI == 1) {
                    v0 = fmaxf(v0 + bias[col], 0.f);
                    v1 = fmaxf(v1 + bias[col + 1], 0.f);
                    __half2 p;
                    p.x = __float2half_rn(v0);
                    p.y = __float2half_rn(v1);
                    *reinterpret_cast<__half2*>(Ch + row * N + col) = p;
                } else {
                    __half2 ah = *reinterpret_cast<const __half2*>(addh + row * N + col);
                    __half2 al = *reinterpret_cast<const __half2*>(addl + row * N + col);
                    float2 o;
                    o.x = v0 + bias[col]     + __half2float(ah.x) + __half2float(al.x);
                    o.y = v1 + bias[col + 1] + __half2float(ah.y) + __half2float(al.y);
                    *reinterpret_cast<float2*>(Cf + row * N + col) = o;
                }
            }
        }
}

// ---------------------------------------------------------------------------
// LN2 in-place over d_out rows
// ---------------------------------------------------------------------------
__global__ __launch_bounds__(256) void ln2_inplace_kernel(float* __restrict__ z,
                                                          const float* __restrict__ w,
                                                          const float* __restrict__ b) {
    int ri = blockIdx.x;
    float* zr = z + (size_t)ri * E_;
    int t = threadIdx.x;
    float v[4]; float s = 0.f, s2 = 0.f;
#pragma unroll
    for (int i = 0; i < 4; i++) {
        int c = t + 256 * i;
        float u = zr[c];
        v[i] = u; s += u; s2 += u * u;
    }
    __shared__ float sh[2][8];
#pragma unroll
    for (int o = 16; o > 0; o >>= 1) {
        s  += __shfl_down_sync(0xFFFFFFFFu, s, o);
        s2 += __shfl_down_sync(0xFFFFFFFFu, s2, o);
    }
    int wid = t >> 5, lane = t & 31;
    if (lane == 0) { sh[0][wid] = s; sh[1][wid] = s2; }
    __syncthreads();
    if (t == 0) {
        float a = 0.f, c2 = 0.f;
#pragma unroll
        for (int i = 0; i < 8; i++) { a += sh[0][i]; c2 += sh[1][i]; }
        sh[0][0] = a; sh[1][0] = c2;
    }
    __syncthreads();
    float mean = sh[0][0] * (1.f / E_);
    float var  = sh[1][0] * (1.f / E_) - mean * mean;
    float rs   = rsqrtf(var + 1e-5f);
#pragma unroll
    for (int i = 0; i < 4; i++) {
        int c = t + 256 * i;
        zr[c] = (v[i] - mean) * rs * w[c] + b[c];
    }
}

// ---------------------------------------------------------------------------
// Launch
// ---------------------------------------------------------------------------
extern "C" void kernel_launch(void* const* d_in, const int* in_sizes, int n_in,
                              void* d_out, int out_size) {
    const float* x     = (const float*)d_in[0];
    const float* w_v   = (const float*)d_in[3];
    const float* w_o   = (const float*)d_in[4];
    const float* b_o   = (const float*)d_in[5];
    const float* ln1_w = (const float*)d_in[6];
    const float* ln1_b = (const float*)d_in[7];
    const float* ln2_w = (const float*)d_in[8];
    const float* ln2_b = (const float*)d_in[9];
    const float* w_ff1 = (const float*)d_in[10];
    const float* b_ff1 = (const float*)d_in[11];
    const float* w_ff2 = (const float*)d_in[12];
    const float* b_ff2 = (const float*)d_in[13];
    float* out = (float*)d_out;

    float* p_AOproj;
    __half *p_Sh, *p_h1h, *p_h1l, *p_t, *p_wto, *p_wt1, *p_wt2;
    cudaGetSymbolAddress((void**)&p_AOproj, g_AOproj);
    cudaGetSymbolAddress((void**)&p_Sh, g_Sh);
    cudaGetSymbolAddress((void**)&p_h1h, g_h1h);
    cudaGetSymbolAddress((void**)&p_h1l, g_h1l);
    cudaGetSymbolAddress((void**)&p_t, g_t);
    cudaGetSymbolAddress((void**)&p_wto, g_wto);
    cudaGetSymbolAddress((void**)&p_wt1, g_wt1);
    cudaGetSymbolAddress((void**)&p_wt2, g_wt2);

    cudaFuncSetAttribute(wo_gemm_kernel,    cudaFuncAttributeMaxDynamicSharedMemorySize, 3 * 16384);
    cudaFuncSetAttribute(ff_gemm_kernel<1>, cudaFuncAttributeMaxDynamicSharedMemorySize, 3 * 32768);
    cudaFuncSetAttribute(ff_gemm_kernel<2>, cudaFuncAttributeMaxDynamicSharedMemorySize, 3 * 32768);

    // 0) wv_red; 1) S = x @ wv_red (fp16); 2) w_o transpose
    reduce_wv_kernel<<<E_, DH>>>(w_v);
    gemm_S_kernel<<<ROWS / 16, dim3(64, 4)>>>(x);
    transpose_half_kernel<<<dim3(E_ / 32, E_ / 32), dim3(32, 8)>>>(w_o, E_, E_, p_wto);

    // 3) AOproj = S(1024x1024) @ w_o + b_o   (1-pass fp16)
    wo_gemm_kernel<<<dim3(E_ / 64, E_ / 64), 256, 3 * 16384>>>(
        E_, E_, E_, p_Sh, p_wto, b_o, p_AOproj);

    // 4,5) FF weight transposes
    transpose_half_kernel<<<dim3(HID_ / 32, E_ / 32), dim3(32, 8)>>>(w_ff1, E_, HID_, p_wt1);
    transpose_half_kernel<<<dim3(E_ / 32, HID_ / 32), dim3(32, 8)>>>(w_ff2, HID_, E_, p_wt2);

    // 6) h1 = LN1(AOproj[gather] + x) -> fp16 hi/lo
    add_ln1_kernel<<<ROWS, 256>>>(x, ln1_w, ln1_b);

    // 7) t = relu(h1 @ w_ff1 + b_ff1) -> fp16   (pipelined frags, occ 2)
    ff_gemm_kernel<1><<<dim3(HID_ / 128, ROWS / 128), 256, 3 * 32768>>>(
        ROWS, HID_, E_, p_h1h, p_wt1, b_ff1, nullptr, nullptr, nullptr, p_t);

    // 8) out = t @ w_ff2 + b_ff2 + h1   (pipelined frags, occ 2)
    ff_gemm_kernel<2><<<dim3(E_ / 128, ROWS / 128), 256, 3 * 32768>>>(
        ROWS, E_, HID_, p_t, p_wt2, b_ff2, p_h1h, p_h1l, out, nullptr);

    // 9) LN2 in-place
    ln2_inplace_kernel<<<ROWS, 256>>>(out, ln2_w, ln2_b);
}

// round 13
// speedup vs baseline: 1.0212x; 1.0081x over previous
#include <cuda_runtime.h>
#include <cuda_fp16.h>
#include <cuda_bf16.h>
#include <cstdint>

// Shapes (fixed by the problem)
#define B_   4
#define L_   4096
#define E_   1024
#define HID_ 4096
#define ROWS (B_ * L_)        // 16384
#define DH   64               // head dim
#define HEADS_ 16

// ---------------------------------------------------------------------------
// PTX helpers (sm_103-safe: no tcgen05)
// ---------------------------------------------------------------------------
__device__ __forceinline__ uint32_t smem_to_u32(const void* p) {
    uint32_t a;
    asm("{ .reg .u64 t; cvta.to.shared.u64 t, %1; cvt.u32.u64 %0, t; }" : "=r"(a) : "l"(p));
    return a;
}
#define CP_ASYNC16(dst, src) asm volatile("cp.async.cg.shared.global [%0], [%1], 16;" :: "r"((uint32_t)(dst)), "l"(src) : "memory")
#define CP_COMMIT()          asm volatile("cp.async.commit_group;" ::: "memory")
#define CP_WAIT(N)           asm volatile("cp.async.wait_group %0;" :: "n"(N) : "memory")

#define LDM_X4(r0, r1, r2, r3, addr) \
    asm volatile("ldmatrix.sync.aligned.m8n8.x4.shared.b16 {%0,%1,%2,%3}, [%4];" \
        : "=r"(r0), "=r"(r1), "=r"(r2), "=r"(r3) : "r"(addr))

__device__ __forceinline__ void mma_fp16(float* c, const uint32_t* a, const uint32_t* b) {
    asm volatile("mma.sync.aligned.m16n8k16.row.col.f32.f16.f16.f32 "
        "{%0,%1,%2,%3}, {%4,%5,%6,%7}, {%8,%9}, {%0,%1,%2,%3};"
        : "+f"(c[0]), "+f"(c[1]), "+f"(c[2]), "+f"(c[3])
        : "r"(a[0]), "r"(a[1]), "r"(a[2]), "r"(a[3]), "r"(b[0]), "r"(b[1]));
}

// Rows are 128B wide; XOR 16B columns with (row & 7) -> conflict-free ldmatrix
#define SWZOFF(row, col16) (((uint32_t)(row) * 128u) + ((((uint32_t)(col16)) ^ ((uint32_t)(row) & 7u)) << 4))

// ---------------------------------------------------------------------------
// Scratch (device globals)
// ---------------------------------------------------------------------------
__device__ float g_wvred[E_ * DH];
__device__ __half g_Sh[E_ * E_];                   // S viewed as 1024x1024 (fp16)
__device__ float g_AOproj[B_ * 256 * E_];
__device__ __half g_h1h[(size_t)ROWS * E_];
__device__ __half g_h1l[(size_t)ROWS * E_];
__device__ __half g_t[(size_t)ROWS * HID_];
__device__ __half g_wto[(size_t)E_ * E_];
__device__ __half g_wt1[(size_t)HID_ * E_];
__device__ __half g_wt2[(size_t)HID_ * E_];

// ---------------------------------------------------------------------------
// wv_red[e,d] = sum_h w_v[e, h*64+d]
// ---------------------------------------------------------------------------
__global__ void reduce_wv_kernel(const float* __restrict__ w_v) {
    int e = blockIdx.x, d = threadIdx.x;
    const float* row = w_v + (size_t)e * E_;
    float s = 0.f;
#pragma unroll
    for (int h = 0; h < HEADS_; h++) s += row[h * DH + d];
    g_wvred[e * DH + d] = s;
}

// ---------------------------------------------------------------------------
// S = x @ wv_red  (16384 x 64, K=1024) -> fp16; 32 rows/block, 8 rows/thread
// ---------------------------------------------------------------------------
__global__ __launch_bounds__(256) void gemm_S_kernel(const float* __restrict__ x) {
    int d = threadIdx.x;                 // 0..63
    int mi = threadIdx.y;                // 0..3
    size_t m0 = (size_t)blockIdx.x * 32 + mi * 8;
    const float* xb = x + m0 * E_;
    float a[8] = {};
#pragma unroll 2
    for (int k = 0; k < E_; k++) {
        float w = g_wvred[k * DH + d];
#pragma unroll
        for (int j = 0; j < 8; j++)
            a[j] = fmaf(xb[(size_t)j * E_ + k], w, a[j]);
    }
#pragma unroll
    for (int j = 0; j < 8; j++)
        g_Sh[(m0 + j) * DH + d] = __float2half_rn(a[j]);
}

// ---------------------------------------------------------------------------
// Transpose fp32 -> fp16 (single). T[c, r] = half(W[r, c])
// ---------------------------------------------------------------------------
__global__ __launch_bounds__(256) void transpose_half_kernel(
    const float* __restrict__ W, int R, int C, __half* __restrict__ T) {
    __shared__ float tile[32][33];
    int r0 = blockIdx.y * 32, c0 = blockIdx.x * 32;
    int tx = threadIdx.x, ty = threadIdx.y;
#pragma unroll
    for (int j = 0; j < 4; j++)
        tile[ty + 8 * j][tx] = W[(size_t)(r0 + ty + 8 * j) * C + c0 + tx];
    __syncthreads();
#pragma unroll
    for (int j = 0; j < 4; j++) {
        size_t o = (size_t)(c0 + ty + 8 * j) * R + r0 + tx;
        T[o] = __float2half_rn(tile[tx][ty + 8 * j]);
    }
}

// ---------------------------------------------------------------------------
// h1 = LN1(AOproj[gather] + x) -> fp16 hi + fp16 lo; float4-vectorized
// thread t handles cols [4t, 4t+4)
// ---------------------------------------------------------------------------
__global__ __launch_bounds__(256) void add_ln1_kernel(const float* __restrict__ x,
                                                      const float* __restrict__ w,
                                                      const float* __restrict__ b) {
    int ri = blockIdx.x;
    int n = ri >> 12, r = ri & 255;
    const float4* pr = (const float4*)(g_AOproj + ((size_t)((n << 8) | r)) * E_);
    const float4* xr = (const float4*)(x + (size_t)ri * E_);
    int t = threadIdx.x;

    float4 pv = pr[t];
    float4 xv = xr[t];
    float v0 = pv.x + xv.x, v1 = pv.y + xv.y, v2 = pv.z + xv.z, v3 = pv.w + xv.w;
    float s  = v0 + v1 + v2 + v3;
    float s2 = v0 * v0 + v1 * v1 + v2 * v2 + v3 * v3;

    __shared__ float sh[2][8];
#pragma unroll
    for (int o = 16; o > 0; o >>= 1) {
        s  += __shfl_down_sync(0xFFFFFFFFu, s, o);
        s2 += __shfl_down_sync(0xFFFFFFFFu, s2, o);
    }
    int wid = t >> 5, lane = t & 31;
    if (lane == 0) { sh[0][wid] = s; sh[1][wid] = s2; }
    __syncthreads();
    if (t == 0) {
        float a = 0.f, c2 = 0.f;
#pragma unroll
        for (int i = 0; i < 8; i++) { a += sh[0][i]; c2 += sh[1][i]; }
        sh[0][0] = a; sh[1][0] = c2;
    }
    __syncthreads();
    float mean = sh[0][0] * (1.f / E_);
    float var  = sh[1][0] * (1.f / E_) - mean * mean;
    float rs   = rsqrtf(var + 1e-5f);

    float4 wv = ((const float4*)w)[t];
    float4 bv = ((const float4*)b)[t];
    float u0 = (v0 - mean) * rs * wv.x + bv.x;
    float u1 = (v1 - mean) * rs * wv.y + bv.y;
    float u2 = (v2 - mean) * rs * wv.z + bv.z;
    float u3 = (v3 - mean) * rs * wv.w + bv.w;

    __half h0 = __float2half_rn(u0), h1v = __float2half_rn(u1);
    __half h2 = __float2half_rn(u2), h3 = __float2half_rn(u3);
    __half2 ph0; ph0.x = h0; ph0.y = h1v;
    __half2 ph1; ph1.x = h2; ph1.y = h3;
    __half2 pl0; pl0.x = __float2half_rn(u0 - __half2float(h0));
    pl0.y = __float2half_rn(u1 - __half2float(h1v));
    __half2 pl1; pl1.x = __float2half_rn(u2 - __half2float(h2));
    pl1.y = __float2half_rn(u3 - __half2float(h3));

    __half2* hrow = (__half2*)(g_h1h + (size_t)ri * E_);
    __half2* lrow = (__half2*)(g_h1l + (size_t)ri * E_);
    hrow[2 * t]     = ph0;
    hrow[2 * t + 1] = ph1;
    lrow[2 * t]     = pl0;
    lrow[2 * t + 1] = pl1;
}

// ---------------------------------------------------------------------------
// 1-pass fp16 GEMM (w_o): 64x64 block, 256 CTAs, occ 2.
// ---------------------------------------------------------------------------
__global__ __launch_bounds__(256, 2)
void wo_gemm_kernel(int M, int N, int K,
                    const __half* __restrict__ Aq, const __half* __restrict__ Bq,
                    const float* __restrict__ bias, float* __restrict__ Cf) {
    constexpr uint32_t ST = 16384u;
    extern __shared__ char smem[];
    uint32_t sbase = smem_to_u32(smem);
    const int tid = threadIdx.x, lane = tid & 31, wid = tid >> 5;
    const int wm = wid & 1, wn = wid >> 1;   // warp tile 32x16

    const __half* A = Aq + (size_t)blockIdx.y * 64 * K;
    const __half* B = Bq + (size_t)blockIdx.x * 64 * K;

    float acc[2][2][4] = {};

    const int la15 = lane & 15;
    const int khA  = lane >> 4;
    const int lbB  = (lane & 7) + ((lane & 16) >> 1);
    const int khB  = (lane >> 3) & 1;

    const int nc = K / 64;

    auto fill = [&](uint32_t stg, int k0) {
        const __half* srcs[2] = {A, B};
#pragma unroll
        for (int s2 = 0; s2 < 2; s2++) {
            const __half* src = srcs[s2] + k0;
            uint32_t base = stg + s2 * 8192u;
#pragma unroll
            for (int j = 0; j < 2; j++) {
                int i = tid * 2 + j;
                int row = i >> 3, col = i & 7;
                CP_ASYNC16(base + SWZOFF(row, col), src + (size_t)row * K + col * 8);
            }
        }
    };

#pragma unroll
    for (int c = 0; c < 3; c++) { fill(sbase + c * ST, c * 64); CP_COMMIT(); }

    for (int c = 0; c < nc; c++) {
        int rem = nc - 1 - c;
        if (rem >= 2)      CP_WAIT(2);
        else if (rem == 1) CP_WAIT(1);
        else               CP_WAIT(0);
        __syncthreads();

        uint32_t st = sbase + (c % 3) * ST;
        uint32_t sA = st, sB = st + 8192u;

#pragma unroll
        for (int ks = 0; ks < 4; ks++) {
            uint32_t a_[2][4], b_[2][2];
            int cA = ks * 2 + khA, cB = ks * 2 + khB;
#pragma unroll
            for (int mt = 0; mt < 2; mt++) {
                int r = wm * 32 + mt * 16 + la15;
                LDM_X4(a_[mt][0], a_[mt][1], a_[mt][2], a_[mt][3], sA + SWZOFF(r, cA));
            }
            {
                int r = wn * 16 + lbB;
                LDM_X4(b_[0][0], b_[0][1], b_[1][0], b_[1][1], sB + SWZOFF(r, cB));
            }
#pragma unroll
            for (int mt = 0; mt < 2; mt++)
#pragma unroll
                for (int nt = 0; nt < 2; nt++)
                    mma_fp16(acc[mt][nt], a_[mt], b_[nt]);
        }
        __syncthreads();

        if (c + 3 < nc) { fill(st, (c + 3) * 64); CP_COMMIT(); }
    }

    int rb = blockIdx.y * 64 + wm * 32 + (lane >> 2);
    int cb = blockIdx.x * 64 + wn * 16 + (lane & 3) * 2;
#pragma unroll
    for (int mt = 0; mt < 2; mt++)
#pragma unroll
        for (int h = 0; h < 2; h++) {
            size_t row = (size_t)rb + mt * 16 + h * 8;
#pragma unroll
            for (int nt = 0; nt < 2; nt++) {
                int col = cb + nt * 8;
                float2 o;
                o.x = acc[mt][nt][2 * h + 0] + bias[col];
                o.y = acc[mt][nt][2 * h + 1] + bias[col + 1];
                *reinterpret_cast<float2*>(Cf + row * N + col) = o;
            }
        }
}

// ---------------------------------------------------------------------------
// FF GEMM: 1-pass fp16, 128x128 block, 8 warps 64x32, BK=64, occ 2.
// A-fragments double-buffered across ks-steps.
// EPI 1: relu(acc+bias) -> fp16 Ch
// EPI 2: acc + bias + (addh+addl) -> fp32 Cf
// ---------------------------------------------------------------------------
template <int EPI>
__global__ __launch_bounds__(256, 2)
void ff_gemm_kernel(int M, int N, int K,
                    const __half* __restrict__ Aq, const __half* __restrict__ Bq,
                    const float* __restrict__ bias,
                    const __half* __restrict__ addh, const __half* __restrict__ addl,
                    float* __restrict__ Cf, __half* __restrict__ Ch) {
    constexpr uint32_t ST = 32768u;
    extern __shared__ char smem[];
    uint32_t sbase = smem_to_u32(smem);
    const int tid = threadIdx.x, lane = tid & 31, wid = tid >> 5;
    const int wm = wid & 1, wn = wid >> 1;

    const __half* A = Aq + (size_t)blockIdx.y * 128 * K;
    const __half* B = Bq + (size_t)blockIdx.x * 128 * K;

    float acc[4][4][4] = {};

    const int la15 = lane & 15;
    const int khA  = lane >> 4;
    const int lbB  = (lane & 7) + ((lane & 16) >> 1);
    const int khB  = (lane >> 3) & 1;

    const int nc = K / 64;

    auto fill = [&](uint32_t stg, int k0) {
        const __half* srcs[2] = {A, B};
#pragma unroll
        for (int s2 = 0; s2 < 2; s2++) {
            const __half* src = srcs[s2] + k0;
            uint32_t base = stg + s2 * 16384u;
#pragma unroll
            for (int j = 0; j < 4; j++) {
                int i = tid * 4 + j;
                int row = i >> 3, col = i & 7;
                CP_ASYNC16(base + SWZOFF(row, col), src + (size_t)row * K + col * 8);
            }
        }
    };

#pragma unroll
    for (int c = 0; c < 3; c++) { fill(sbase + c * ST, c * 64); CP_COMMIT(); }

    for (int c = 0; c < nc; c++) {
        int rem = nc - 1 - c;
        if (rem >= 2)      CP_WAIT(2);
        else if (rem == 1) CP_WAIT(1);
        else               CP_WAIT(0);
        __syncthreads();

        uint32_t st = sbase + (c % 3) * ST;
        uint32_t sA = st, sB = st + 16384u;

        uint32_t a_[2][4][4], b_[4][2];
#pragma unroll
        for (int mt = 0; mt < 4; mt++) {
            int r = wm * 64 + mt * 16 + la15;
            LDM_X4(a_[0][mt][0], a_[0][mt][1], a_[0][mt][2], a_[0][mt][3],
                   sA + SWZOFF(r, khA));
        }

#pragma unroll
        for (int ks = 0; ks < 4; ks++) {
            const int cur = ks & 1, nxt = cur ^ 1;
            int cB = ks * 2 + khB;
#pragma unroll
            for (int np = 0; np < 2; np++) {
                int r = wn * 32 + np * 16 + lbB;
                LDM_X4(b_[2 * np][0], b_[2 * np][1], b_[2 * np + 1][0], b_[2 * np + 1][1],
                       sB + SWZOFF(r, cB));
            }
            if (ks < 3) {
                int cA = (ks + 1) * 2 + khA;
#pragma unroll
                for (int mt = 0; mt < 4; mt++) {
                    int r = wm * 64 + mt * 16 + la15;
                    LDM_X4(a_[nxt][mt][0], a_[nxt][mt][1], a_[nxt][mt][2], a_[nxt][mt][3],
                           sA + SWZOFF(r, cA));
                }
            }
#pragma unroll
            for (int mt = 0; mt < 4; mt++)
#pragma unroll
                for (int nt = 0; nt < 4; nt++)
                    mma_fp16(acc[mt][nt], a_[cur][mt], b_[nt]);
        }
        __syncthreads();

        if (c + 3 < nc) { fill(st, (c + 3) * 64); CP_COMMIT(); }
    }

    int rb = blockIdx.y * 128 + wm * 64 + (lane >> 2);
    int cb = blockIdx.x * 128 + wn * 32 + (lane & 3) * 2;
#pragma unroll
    for (int mt = 0; mt < 4; mt++)
#pragma unroll
        for (int h = 0; h < 2; h++) {
            size_t row = (size_t)rb + mt * 16 + h * 8;
#pragma unroll
            for (int nt = 0; nt < 4; nt++) {
                int col = cb + nt * 8;
                float v0 = acc[mt][nt][2 * h + 0];
                float v1 = acc[mt][nt][2 * h + 1];
                if (EPI == 1) {
                    v0 = fmaxf(v0 + bias[col], 0.f);
                    v1 = fmaxf(v1 + bias[col + 1], 0.f);
                    __half2 p;
                    p.x = __float2half_rn(v0);
                    p.y = __float2half_rn(v1);
                    *reinterpret_cast<__half2*>(Ch + row * N + col) = p;
                } else {
                    __half2 ah = *reinterpret_cast<const __half2*>(addh + row * N + col);
                    __half2 al = *reinterpret_cast<const __half2*>(addl + row * N + col);
                    float2 o;
                    o.x = v0 + bias[col]     + __half2float(ah.x) + __half2float(al.x);
                    o.y = v1 + bias[col + 1] + __half2float(ah.y) + __half2float(al.y);
                    *reinterpret_cast<float2*>(Cf + row * N + col) = o;
                }
            }
        }
}

// ---------------------------------------------------------------------------
// LN2 in-place over d_out rows; float4-vectorized (cols [4t, 4t+4))
// ---------------------------------------------------------------------------
__global__ __launch_bounds__(256) void ln2_inplace_kernel(float* __restrict__ z,
                                                          const float* __restrict__ w,
                                                          const float* __restrict__ b) {
    int ri = blockIdx.x;
    float4* zr = (float4*)(z + (size_t)ri * E_);
    int t = threadIdx.x;

    float4 v = zr[t];
    float s  = v.x + v.y + v.z + v.w;
    float s2 = v.x * v.x + v.y * v.y + v.z * v.z + v.w * v.w;

    __shared__ float sh[2][8];
#pragma unroll
    for (int o = 16; o > 0; o >>= 1) {
        s  += __shfl_down_sync(0xFFFFFFFFu, s, o);
        s2 += __shfl_down_sync(0xFFFFFFFFu, s2, o);
    }
    int wid = t >> 5, lane = t & 31;
    if (lane == 0) { sh[0][wid] = s; sh[1][wid] = s2; }
    __syncthreads();
    if (t == 0) {
        float a = 0.f, c2 = 0.f;
#pragma unroll
        for (int i = 0; i < 8; i++) { a += sh[0][i]; c2 += sh[1][i]; }
        sh[0][0] = a; sh[1][0] = c2;
    }
    __syncthreads();
    float mean = sh[0][0] * (1.f / E_);
    float var  = sh[1][0] * (1.f / E_) - mean * mean;
    float rs   = rsqrtf(var + 1e-5f);

    float4 wv = ((const float4*)w)[t];
    float4 bv = ((const float4*)b)[t];
    float4 o;
    o.x = (v.x - mean) * rs * wv.x + bv.x;
    o.y = (v.y - mean) * rs * wv.y + bv.y;
    o.z = (v.z - mean) * rs * wv.z + bv.z;
    o.w = (v.w - mean) * rs * wv.w + bv.w;
    zr[t] = o;
}

// ---------------------------------------------------------------------------
// Launch
// ---------------------------------------------------------------------------
extern "C" void kernel_launch(void* const* d_in, const int* in_sizes, int n_in,
                              void* d_out, int out_size) {
    const float* x     = (const float*)d_in[0];
    const float* w_v   = (const float*)d_in[3];
    const float* w_o   = (const float*)d_in[4];
    const float* b_o   = (const float*)d_in[5];
    const float* ln1_w = (const float*)d_in[6];
    const float* ln1_b = (const float*)d_in[7];
    const float* ln2_w = (const float*)d_in[8];
    const float* ln2_b = (const float*)d_in[9];
    const float* w_ff1 = (const float*)d_in[10];
    const float* b_ff1 = (const float*)d_in[11];
    const float* w_ff2 = (const float*)d_in[12];
    const float* b_ff2 = (const float*)d_in[13];
    float* out = (float*)d_out;

    float* p_AOproj;
    __half *p_Sh, *p_h1h, *p_h1l, *p_t, *p_wto, *p_wt1, *p_wt2;
    cudaGetSymbolAddress((void**)&p_AOproj, g_AOproj);
    cudaGetSymbolAddress((void**)&p_Sh, g_Sh);
    cudaGetSymbolAddress((void**)&p_h1h, g_h1h);
    cudaGetSymbolAddress((void**)&p_h1l, g_h1l);
    cudaGetSymbolAddress((void**)&p_t, g_t);
    cudaGetSymbolAddress((void**)&p_wto, g_wto);
    cudaGetSymbolAddress((void**)&p_wt1, g_wt1);
    cudaGetSymbolAddress((void**)&p_wt2, g_wt2);

    cudaFuncSetAttribute(wo_gemm_kernel,    cudaFuncAttributeMaxDynamicSharedMemorySize, 3 * 16384);
    cudaFuncSetAttribute(ff_gemm_kernel<1>, cudaFuncAttributeMaxDynamicSharedMemorySize, 3 * 32768);
    cudaFuncSetAttribute(ff_gemm_kernel<2>, cudaFuncAttributeMaxDynamicSharedMemorySize, 3 * 32768);

    // 0) wv_red; 1) S = x @ wv_red (fp16); 2) w_o transpose
    reduce_wv_kernel<<<E_, DH>>>(w_v);
    gemm_S_kernel<<<ROWS / 32, dim3(64, 4)>>>(x);
    transpose_half_kernel<<<dim3(E_ / 32, E_ / 32), dim3(32, 8)>>>(w_o, E_, E_, p_wto);

    // 3) AOproj = S(1024x1024) @ w_o + b_o   (1-pass fp16)
    wo_gemm_kernel<<<dim3(E_ / 64, E_ / 64), 256, 3 * 16384>>>(
        E_, E_, E_, p_Sh, p_wto, b_o, p_AOproj);

    // 4,5) FF weight transposes
    transpose_half_kernel<<<dim3(HID_ / 32, E_ / 32), dim3(32, 8)>>>(w_ff1, E_, HID_, p_wt1);
    transpose_half_kernel<<<dim3(E_ / 32, HID_ / 32), dim3(32, 8)>>>(w_ff2, HID_, E_, p_wt2);

    // 6) h1 = LN1(AOproj[gather] + x) -> fp16 hi/lo   (vectorized)
    add_ln1_kernel<<<ROWS, 256>>>(x, ln1_w, ln1_b);

    // 7) t = relu(h1 @ w_ff1 + b_ff1) -> fp16
    ff_gemm_kernel<1><<<dim3(HID_ / 128, ROWS / 128), 256, 3 * 32768>>>(
        ROWS, HID_, E_, p_h1h, p_wt1, b_ff1, nullptr, nullptr, nullptr, p_t);

    // 8) out = t @ w_ff2 + b_ff2 + h1
    ff_gemm_kernel<2><<<dim3(E_ / 128, ROWS / 128), 256, 3 * 32768>>>(
        ROWS, E_, HID_, p_t, p_wt2, b_ff2, p_h1h, p_h1l, out, nullptr);

    // 9) LN2 in-place   (vectorized)
    ln2_inplace_kernel<<<ROWS, 256>>>(out, ln2_w, ln2_b);
}